// round 5
// baseline (speedup 1.0000x reference)
#include <cuda_runtime.h>

#define TT   1024
#define BB   512
#define IND  64
#define HIDD 256
#define OUTD 32

// Exact-order LIF net. Dot products: single-accumulator ascending-k
// __fmaf_rn chain; bias added after (separate rounding). LIF update:
// fma(beta, mem, cur) - reset  (XLA contracts the mul+add; the reset*1.0
// product is exact so its handling is value-neutral). Spike compare on
// (mem - 1.0f) > 0. Any extra/missing rounding flips near-threshold spikes.

__global__ void __launch_bounds__(256, 2) snn_kernel(
    const float* __restrict__ x,    // [T, B, IN]
    const float* __restrict__ W1,   // [HID, IN]
    const float* __restrict__ b1,   // [HID]
    const float* __restrict__ W2,   // [OUT, HID]
    const float* __restrict__ b2,   // [OUT]
    float* __restrict__ out)        // [2, T, B, OUT] (spk2 then mem2)
{
    __shared__ __align__(16) float xs[2][IND];       // double-buffered x_t
    __shared__ __align__(16) float spk_s[HIDD];      // layer-1 spikes
    __shared__ __align__(16) float w2s[HIDD][OUTD];  // W2 transposed: [k][o]

    const int b   = blockIdx.x;   // one batch element per CTA
    const int tid = threadIdx.x;  // thread h owns hidden unit h

    // stage W2 transposed into smem (conflict-free for lane=o reads)
    #pragma unroll
    for (int e = tid; e < OUTD * HIDD; e += 256) {
        int o = e / HIDD;
        int k = e % HIDD;
        w2s[k][o] = W2[e];
    }

    // W1 row of this hidden unit in registers (64 regs)
    float w1r[IND];
    #pragma unroll
    for (int k = 0; k < IND; k++) w1r[k] = W1[tid * IND + k];

    const float b1h = b1[tid];
    const float b2o = b2[tid & 31];

    float mem1 = 0.0f;
    float mem2 = 0.0f;

    // stage x_0
    if (tid < 16) {
        ((float4*)xs[0])[tid] = ((const float4*)(x + (size_t)b * IND))[tid];
    }
    __syncthreads();

    for (int t = 0; t < TT; t++) {
        // ---- layer 1: sequential ascending-k fma chain, bias added after ----
        const float* xv = xs[t & 1];
        float acc = 0.0f;
        #pragma unroll
        for (int k = 0; k < IND; k++) acc = __fmaf_rn(xv[k], w1r[k], acc);
        float cur1 = __fadd_rn(acc, b1h);

        // LIF1: reset from previous mem (detached); contracted fma update
        float reset1 = (mem1 > 1.0f) ? 1.0f : 0.0f;
        mem1 = __fsub_rn(__fmaf_rn(0.92f, mem1, cur1), reset1);
        spk_s[tid] = (__fsub_rn(mem1, 1.0f) > 0.0f) ? 1.0f : 0.0f;
        __syncthreads();

        // prefetch x_{t+1} into the other buffer (16 threads, float4)
        if (t + 1 < TT && tid < 16) {
            ((float4*)xs[(t + 1) & 1])[tid] =
                ((const float4*)(x + ((size_t)(t + 1) * BB + b) * IND))[tid];
        }

        // ---- layer 2: one thread per output, sequential 256-fma chain ----
        if (tid < OUTD) {
            float acc2 = 0.0f;
            #pragma unroll 32
            for (int k = 0; k < HIDD; k++)
                acc2 = __fmaf_rn(spk_s[k], w2s[k][tid], acc2);
            float cur2 = __fadd_rn(acc2, b2o);

            float reset2 = (mem2 > 1.0f) ? 1.0f : 0.0f;
            mem2 = __fsub_rn(__fmaf_rn(0.92f, mem2, cur2), reset2);
            float spk2 = (__fsub_rn(mem2, 1.0f) > 0.0f) ? 1.0f : 0.0f;

            size_t idx = ((size_t)t * BB + b) * OUTD + tid;
            out[idx] = spk2;                              // spk2_rec
            out[(size_t)TT * BB * OUTD + idx] = mem2;     // mem2_rec
        }
        __syncthreads();  // protect spk_s before next step overwrites
    }
}

extern "C" void kernel_launch(void* const* d_in, const int* in_sizes, int n_in,
                              void* d_out, int out_size) {
    const float* x  = (const float*)d_in[0];  // spike_input [1024,512,64]
    const float* W1 = (const float*)d_in[1];  // [256,64]
    const float* b1 = (const float*)d_in[2];  // [256]
    const float* W2 = (const float*)d_in[3];  // [32,256]
    const float* b2 = (const float*)d_in[4];  // [32]
    float* out = (float*)d_out;               // 2*1024*512*32 floats

    snn_kernel<<<BB, 256>>>(x, W1, b1, W2, b2, out);
}

// round 6
// speedup vs baseline: 3.1553x; 3.1553x over previous
#include <cuda_runtime.h>

#define TT   1024
#define BB   512
#define IND  64
#define HIDD 256
#define OUTD 32
#define TS   32    // timestep tile

// Rounding contract (matches reference bit-for-bit, rel_err 7.6e-8 at R5):
//  - every dot product: single accumulator, ascending-k __fmaf_rn chain
//  - bias added after, separate __fadd_rn
//  - LIF: mem = __fmaf_rn(0.92, mem, cur) - reset   (reset detached, from prev mem)
//  - spike: (mem - 1.0f) > 0
// Parallelism only across independent elements/timesteps, never within a chain.

__global__ void __launch_bounds__(256, 2) snn_kernel(
    const float* __restrict__ x,    // [T, B, IN]
    const float* __restrict__ W1,   // [HID, IN]
    const float* __restrict__ b1,   // [HID]
    const float* __restrict__ W2,   // [OUT, HID]
    const float* __restrict__ b2,   // [OUT]
    float* __restrict__ out)        // [2, T, B, OUT] (spk2 then mem2)
{
    __shared__ __align__(16) float xt[TS][IND];        // x tile          (8 KB)
    __shared__ __align__(16) float spk[TS][HIDD];      // layer-1 spikes (32 KB)
    __shared__ __align__(16) float w2s[HIDD][OUTD];    // W2 transposed  (32 KB)
    __shared__ __align__(16) float red[TS][OUTD];      // cur2 staging    (4 KB)

    const int b   = blockIdx.x;   // one batch element per CTA
    const int tid = threadIdx.x;  // layer 1: thread h owns hidden unit h
    const int o   = tid & 31;     // layer 2: output index
    const int tg  = tid >> 5;     // layer 2: t-group (handles t = tg + 8j)

    // stage W2 transposed: w2s[k][o]
    #pragma unroll
    for (int e = tid; e < OUTD * HIDD; e += 256) {
        w2s[e % HIDD][e / HIDD] = W2[e];
    }

    // W1 row of this hidden unit in registers
    float w1r[IND];
    #pragma unroll
    for (int k = 0; k < IND; k++) w1r[k] = W1[tid * IND + k];

    const float b1h = b1[tid];
    const float b2o = b2[o];

    float mem1 = 0.0f;
    float mem2 = 0.0f;

    for (int t0 = 0; t0 < TT; t0 += TS) {
        // ---- stage x tile: TS*IND floats = 512 float4, 2 per thread ----
        {
            const float4* xg = (const float4*)(x + ((size_t)t0 * BB + b) * IND);
            // row r of tile lives at x + (t0+r)*BB*IND + b*IND; rows are 16 float4
            #pragma unroll
            for (int i = 0; i < 2; i++) {
                int e = tid + i * 256;        // float4 index in tile
                int r = e >> 4, c = e & 15;   // row, col(float4)
                ((float4*)xt)[e] =
                    ((const float4*)(x + ((size_t)(t0 + r) * BB + b) * IND))[c];
            }
            (void)xg;
        }
        __syncthreads();

        // ---- layer 1 + mem1 recurrence (fused, ascending t) ----
        // thread h: for each t, 64-fma chain (x via float4 broadcast), then LIF1
        for (int t = 0; t < TS; t++) {
            const float4* xv = (const float4*)xt[t];
            float acc = 0.0f;
            #pragma unroll
            for (int kc = 0; kc < IND / 4; kc++) {
                float4 v = xv[kc];
                acc = __fmaf_rn(v.x, w1r[kc * 4 + 0], acc);
                acc = __fmaf_rn(v.y, w1r[kc * 4 + 1], acc);
                acc = __fmaf_rn(v.z, w1r[kc * 4 + 2], acc);
                acc = __fmaf_rn(v.w, w1r[kc * 4 + 3], acc);
            }
            float cur1 = __fadd_rn(acc, b1h);
            float reset1 = (mem1 > 1.0f) ? 1.0f : 0.0f;
            mem1 = __fsub_rn(__fmaf_rn(0.92f, mem1, cur1), reset1);
            spk[t][tid] = (__fsub_rn(mem1, 1.0f) > 0.0f) ? 1.0f : 0.0f;
        }
        __syncthreads();

        // ---- layer 2: 32t x 32o = 1024 independent 256-fma chains ----
        // thread (o, tg) runs 4 chains: t = tg, tg+8, tg+16, tg+24.
        // w2 loads shared across the 4 chains; spk via float4 broadcast.
        {
            float a0 = 0.0f, a1 = 0.0f, a2 = 0.0f, a3 = 0.0f;
            const float4* s0 = (const float4*)spk[tg];
            const float4* s1 = (const float4*)spk[tg + 8];
            const float4* s2 = (const float4*)spk[tg + 16];
            const float4* s3 = (const float4*)spk[tg + 24];
            for (int kc = 0; kc < HIDD / 4; kc++) {
                float wa = w2s[kc * 4 + 0][o];
                float wb = w2s[kc * 4 + 1][o];
                float wc = w2s[kc * 4 + 2][o];
                float wd = w2s[kc * 4 + 3][o];
                float4 v0 = s0[kc], v1 = s1[kc], v2 = s2[kc], v3 = s3[kc];
                a0 = __fmaf_rn(v0.x, wa, a0); a0 = __fmaf_rn(v0.y, wb, a0);
                a0 = __fmaf_rn(v0.z, wc, a0); a0 = __fmaf_rn(v0.w, wd, a0);
                a1 = __fmaf_rn(v1.x, wa, a1); a1 = __fmaf_rn(v1.y, wb, a1);
                a1 = __fmaf_rn(v1.z, wc, a1); a1 = __fmaf_rn(v1.w, wd, a1);
                a2 = __fmaf_rn(v2.x, wa, a2); a2 = __fmaf_rn(v2.y, wb, a2);
                a2 = __fmaf_rn(v2.z, wc, a2); a2 = __fmaf_rn(v2.w, wd, a2);
                a3 = __fmaf_rn(v3.x, wa, a3); a3 = __fmaf_rn(v3.y, wb, a3);
                a3 = __fmaf_rn(v3.z, wc, a3); a3 = __fmaf_rn(v3.w, wd, a3);
            }
            red[tg][o]      = __fadd_rn(a0, b2o);
            red[tg + 8][o]  = __fadd_rn(a1, b2o);
            red[tg + 16][o] = __fadd_rn(a2, b2o);
            red[tg + 24][o] = __fadd_rn(a3, b2o);
        }
        __syncthreads();

        // ---- mem2 recurrence + store (warp 0; others proceed to next tile
        //      and wait at the post-xt-load barrier) ----
        if (tid < OUTD) {
            #pragma unroll 4
            for (int t = 0; t < TS; t++) {
                float cur2 = red[t][tid];
                float reset2 = (mem2 > 1.0f) ? 1.0f : 0.0f;
                mem2 = __fsub_rn(__fmaf_rn(0.92f, mem2, cur2), reset2);
                float spk2 = (__fsub_rn(mem2, 1.0f) > 0.0f) ? 1.0f : 0.0f;
                size_t idx = ((size_t)(t0 + t) * BB + b) * OUTD + tid;
                out[idx] = spk2;                              // spk2_rec
                out[(size_t)TT * BB * OUTD + idx] = mem2;     // mem2_rec
            }
        }
        __syncthreads();  // red consumed; spk/xt free for next tile
    }
}

extern "C" void kernel_launch(void* const* d_in, const int* in_sizes, int n_in,
                              void* d_out, int out_size) {
    const float* x  = (const float*)d_in[0];  // spike_input [1024,512,64]
    const float* W1 = (const float*)d_in[1];  // [256,64]
    const float* b1 = (const float*)d_in[2];  // [256]
    const float* W2 = (const float*)d_in[3];  // [32,256]
    const float* b2 = (const float*)d_in[4];  // [32]
    float* out = (float*)d_out;               // 2*1024*512*32 floats

    snn_kernel<<<BB, 256>>>(x, W1, b1, W2, b2, out);
}

// round 7
// speedup vs baseline: 3.6102x; 1.1442x over previous
#include <cuda_runtime.h>

#define TT   1024
#define BB   512
#define IND  64
#define HIDD 256
#define OUTD 32
#define TS   32    // timestep tile

typedef unsigned long long u64;

// Rounding contract (verified bitwise vs reference, rel_err 7.6e-8):
//  - every dot product: single accumulator, ascending-k __fmaf_rn chain
//  - bias added after, separate __fadd_rn
//  - LIF: mem = __fmaf_rn(0.92, mem, cur) - reset (reset detached, prev mem)
//  - spike: (mem - 1.0f) > 0
// Exploits (bitwise-neutral):
//  - fma.rn.f32x2 packs the independent t / t+1 chains (per-half IEEE rn)
//  - spk in {0,1}: fma(0,w,acc)==acc, fma(1,w,acc)==__fadd_rn(w,acc) exactly,
//    so layer 2 = sparse ascending-k sum over ballot-mask set bits.

__device__ __forceinline__ u64 ffma2(u64 a, u64 b, u64 c) {
    u64 d;
    asm("fma.rn.f32x2 %0, %1, %2, %3;" : "=l"(d) : "l"(a), "l"(b), "l"(c));
    return d;
}
__device__ __forceinline__ u64 dup2(float w) {   // (w, w) packed
    u64 d;
    asm("mov.b64 %0, {%1, %1};" : "=l"(d) : "f"(w));
    return d;
}

__global__ void __launch_bounds__(256, 2) snn_kernel(
    const float* __restrict__ x,    // [T, B, IN]
    const float* __restrict__ W1,   // [HID, IN]
    const float* __restrict__ b1,   // [HID]
    const float* __restrict__ W2,   // [OUT, HID]
    const float* __restrict__ b2,   // [OUT]
    float* __restrict__ out)        // [2, T, B, OUT] (spk2 then mem2)
{
    __shared__ __align__(16) float2   xq[TS / 2][IND];   // (t even, t odd) pairs, 8 KB
    __shared__ __align__(16) unsigned msk[TS][8];        // spike bitmasks, 1 KB
    __shared__ __align__(16) float    w2s[HIDD][OUTD];   // W2 transposed, 32 KB
    __shared__ __align__(16) float    red[TS][OUTD];     // cur2 staging, 4 KB

    const int b   = blockIdx.x;   // one batch element per CTA
    const int tid = threadIdx.x;  // layer 1: thread h owns hidden unit h
    const int o   = tid & 31;     // layer 2: output index
    const int tg  = tid >> 5;     // layer 2: t-group

    // stage W2 transposed: w2s[k][o]
    for (int e = tid; e < OUTD * HIDD; e += 256) {
        w2s[e % HIDD][e / HIDD] = W2[e];
    }

    // W1 row of this hidden unit in registers
    float w1r[IND];
    #pragma unroll
    for (int k = 0; k < IND; k++) w1r[k] = W1[tid * IND + k];

    const float b1h = b1[tid];
    const float b2o = b2[o];

    float mem1 = 0.0f;
    float mem2 = 0.0f;

    const int stp = tid >> 4;     // staging: t-pair index 0..15
    const int skc = tid & 15;     // staging: float4 chunk 0..15

    for (int t0 = 0; t0 < TT; t0 += TS) {
        // ---- stage x tile as (t,t+1) interleaved pairs ----
        {
            const float4 a = ((const float4*)(x + ((size_t)(t0 + 2 * stp)     * BB + b) * IND))[skc];
            const float4 c = ((const float4*)(x + ((size_t)(t0 + 2 * stp + 1) * BB + b) * IND))[skc];
            xq[stp][skc * 4 + 0] = make_float2(a.x, c.x);
            xq[stp][skc * 4 + 1] = make_float2(a.y, c.y);
            xq[stp][skc * 4 + 2] = make_float2(a.z, c.z);
            xq[stp][skc * 4 + 3] = make_float2(a.w, c.w);
        }
        __syncthreads();

        // ---- layer 1 (paired f32x2 chains) + mem1 recurrence + ballot ----
        for (int g = 0; g < 8; g++) {        // t = 4g .. 4g+3
            const ulonglong2* r0 = (const ulonglong2*)xq[2 * g];
            const ulonglong2* r1 = (const ulonglong2*)xq[2 * g + 1];
            u64 acc0 = 0ull, acc1 = 0ull;
            #pragma unroll
            for (int kc = 0; kc < IND / 2; kc++) {
                ulonglong2 v0 = r0[kc];      // pairs for k=2kc, 2kc+1 (t=4g,4g+1)
                ulonglong2 v1 = r1[kc];      // same, t=4g+2,4g+3
                u64 wa = dup2(w1r[2 * kc]);
                u64 wb = dup2(w1r[2 * kc + 1]);
                acc0 = ffma2(v0.x, wa, acc0);
                acc0 = ffma2(v0.y, wb, acc0);
                acc1 = ffma2(v1.x, wa, acc1);
                acc1 = ffma2(v1.y, wb, acc1);
            }
            float c4[4];
            c4[0] = ((float2*)&acc0)->x;  c4[1] = ((float2*)&acc0)->y;
            c4[2] = ((float2*)&acc1)->x;  c4[3] = ((float2*)&acc1)->y;
            #pragma unroll
            for (int i = 0; i < 4; i++) {   // LIF ascending t
                float cur1 = __fadd_rn(c4[i], b1h);
                float reset1 = (mem1 > 1.0f) ? 1.0f : 0.0f;
                mem1 = __fsub_rn(__fmaf_rn(0.92f, mem1, cur1), reset1);
                bool sp = (__fsub_rn(mem1, 1.0f) > 0.0f);
                unsigned bal = __ballot_sync(0xffffffffu, sp);
                if ((tid & 31) == 0) msk[4 * g + i][tid >> 5] = bal;
            }
        }
        __syncthreads();

        // ---- layer 2: sparse ascending-k sum over warp-uniform masks ----
        #pragma unroll
        for (int j = 0; j < 4; j++) {
            const int t = tg + 8 * j;
            float acc = 0.0f;
            #pragma unroll
            for (int w = 0; w < 8; w++) {
                unsigned m = msk[t][w];               // uniform broadcast
                while (m) {                            // uniform branch
                    int k = __ffs(m) - 1;
                    acc = __fadd_rn(acc, w2s[w * 32 + k][o]);
                    m &= m - 1;
                }
            }
            red[t][o] = __fadd_rn(acc, b2o);
        }
        __syncthreads();

        // ---- mem2 recurrence + store (warp 0) ----
        if (tid < OUTD) {
            #pragma unroll 4
            for (int t = 0; t < TS; t++) {
                float cur2 = red[t][tid];
                float reset2 = (mem2 > 1.0f) ? 1.0f : 0.0f;
                mem2 = __fsub_rn(__fmaf_rn(0.92f, mem2, cur2), reset2);
                float spk2 = (__fsub_rn(mem2, 1.0f) > 0.0f) ? 1.0f : 0.0f;
                size_t idx = ((size_t)(t0 + t) * BB + b) * OUTD + tid;
                out[idx] = spk2;                              // spk2_rec
                out[(size_t)TT * BB * OUTD + idx] = mem2;     // mem2_rec
            }
        }
        __syncthreads();  // red consumed; xq/msk free for next tile
    }
}

extern "C" void kernel_launch(void* const* d_in, const int* in_sizes, int n_in,
                              void* d_out, int out_size) {
    const float* x  = (const float*)d_in[0];  // spike_input [1024,512,64]
    const float* W1 = (const float*)d_in[1];  // [256,64]
    const float* b1 = (const float*)d_in[2];  // [256]
    const float* W2 = (const float*)d_in[3];  // [32,256]
    const float* b2 = (const float*)d_in[4];  // [32]
    float* out = (float*)d_out;               // 2*1024*512*32 floats

    snn_kernel<<<BB, 256>>>(x, W1, b1, W2, b2, out);
}